// round 1
// baseline (speedup 1.0000x reference)
#include <cuda_runtime.h>
#include <math.h>

#define T_  512
#define B_  64
#define E_  256
#define H_  256
#define TB_ (T_ * B_)          // 32768
#define NC_ 128                // recurrence CTAs (each owns 2 h-columns)

// ---------------- static device scratch (no allocations allowed) ----------------
__device__ float g_Q  [TB_ * E_];          // 33.5 MB
__device__ float g_K  [TB_ * E_];          // 33.5 MB
__device__ float g_S  [B_ * T_ * T_];      // 67 MB
__device__ float g_CTX[TB_ * E_];          // 33.5 MB
__device__ float g_CP [TB_ * H_];          // 33.5 MB
__device__ float g_PRE[(long)TB_ * 4 * H_];// 134 MB
__device__ float g_WhP[NC_ * 256 * 8];     // packed recurrent weights per CTA
__device__ float g_hT [H_ * B_];           // h transposed [j][b]
__device__ unsigned g_bar;

// ---------------- generic fp32 tiled GEMM ----------------
// C[M,N] = A[M,K] @ B  (+bias) (+=C). NT: B given row-major [N,K] (C += A·B^T).
// blockIdx.z batching via sA/sB/sC element strides.
#define BM 64
#define BN 64
#define BK 16

template<bool NT, bool ACCUM, bool BIAS>
__global__ void __launch_bounds__(256) gemm_k(
    const float* __restrict__ A, const float* __restrict__ B,
    float* __restrict__ C, const float* __restrict__ bias,
    int M, int N, int K, int lda, int ldb, int ldc,
    long sA, long sB, long sC)
{
    A += (long)blockIdx.z * sA;
    B += (long)blockIdx.z * sB;
    C += (long)blockIdx.z * sC;

    __shared__ __align__(16) float As[BK][BM];
    __shared__ __align__(16) float Bs[BK][BN];

    const int tid = threadIdx.x;
    const int m0 = blockIdx.y * BM;
    const int n0 = blockIdx.x * BN;
    const int tx = tid & 15, ty = tid >> 4;

    const int am  = tid >> 2;   // 0..63
    const int akq = tid & 3;    // 0..3

    float acc[4][4];
    #pragma unroll
    for (int i = 0; i < 4; ++i)
        #pragma unroll
        for (int j = 0; j < 4; ++j) acc[i][j] = 0.f;

    for (int k0 = 0; k0 < K; k0 += BK) {
        float4 va = *(const float4*)(A + (long)(m0 + am) * lda + k0 + akq * 4);
        float4 vb;
        if (NT) vb = *(const float4*)(B + (long)(n0 + (tid >> 2)) * ldb + k0 + (tid & 3) * 4);
        else    vb = *(const float4*)(B + (long)(k0 + (tid >> 4)) * ldb + n0 + (tid & 15) * 4);

        __syncthreads();
        As[akq * 4 + 0][am] = va.x; As[akq * 4 + 1][am] = va.y;
        As[akq * 4 + 2][am] = va.z; As[akq * 4 + 3][am] = va.w;
        if (NT) {
            int bn = tid >> 2, bkq = tid & 3;
            Bs[bkq * 4 + 0][bn] = vb.x; Bs[bkq * 4 + 1][bn] = vb.y;
            Bs[bkq * 4 + 2][bn] = vb.z; Bs[bkq * 4 + 3][bn] = vb.w;
        } else {
            *(float4*)&Bs[tid >> 4][(tid & 15) * 4] = vb;
        }
        __syncthreads();

        #pragma unroll
        for (int k = 0; k < BK; ++k) {
            float4 a = *(const float4*)&As[k][ty * 4];
            float4 b = *(const float4*)&Bs[k][tx * 4];
            acc[0][0] += a.x * b.x; acc[0][1] += a.x * b.y; acc[0][2] += a.x * b.z; acc[0][3] += a.x * b.w;
            acc[1][0] += a.y * b.x; acc[1][1] += a.y * b.y; acc[1][2] += a.y * b.z; acc[1][3] += a.y * b.w;
            acc[2][0] += a.z * b.x; acc[2][1] += a.z * b.y; acc[2][2] += a.z * b.z; acc[2][3] += a.z * b.w;
            acc[3][0] += a.w * b.x; acc[3][1] += a.w * b.y; acc[3][2] += a.w * b.z; acc[3][3] += a.w * b.w;
        }
    }

    #pragma unroll
    for (int i = 0; i < 4; ++i) {
        int m = m0 + ty * 4 + i;
        float* cp = C + (long)m * ldc + n0 + tx * 4;
        float4 r = make_float4(acc[i][0], acc[i][1], acc[i][2], acc[i][3]);
        if (BIAS) {
            const float* bp = bias + n0 + tx * 4;
            r.x += bp[0]; r.y += bp[1]; r.z += bp[2]; r.w += bp[3];
        }
        if (ACCUM) {
            float4 o = *(const float4*)cp;
            r.x += o.x; r.y += o.y; r.z += o.z; r.w += o.w;
        }
        *(float4*)cp = r;
    }
}

// ---------------- softmax over rows of length 512 (scale 1/sqrt(256)) ----------------
__global__ void __launch_bounds__(128) softmax_k(float* __restrict__ S)
{
    float* p = S + (long)blockIdx.x * 512;
    int tid = threadIdx.x;
    float v[4];
    float m = -1e30f;
    #pragma unroll
    for (int i = 0; i < 4; ++i) { v[i] = p[tid + 128 * i] * 0.0625f; m = fmaxf(m, v[i]); }
    __shared__ float red[128];
    red[tid] = m; __syncthreads();
    for (int s = 64; s > 0; s >>= 1) { if (tid < s) red[tid] = fmaxf(red[tid], red[tid + s]); __syncthreads(); }
    m = red[0]; __syncthreads();
    float sum = 0.f;
    #pragma unroll
    for (int i = 0; i < 4; ++i) { v[i] = expf(v[i] - m); sum += v[i]; }
    red[tid] = sum; __syncthreads();
    for (int s = 64; s > 0; s >>= 1) { if (tid < s) red[tid] += red[tid + s]; __syncthreads(); }
    float inv = 1.f / red[0];
    #pragma unroll
    for (int i = 0; i < 4; ++i) p[tid + 128 * i] = v[i] * inv;
}

// ---------------- pack recurrent weights + init state ----------------
// g_WhP[c][hh][q], q = g*2+jj, column j = c*2+jj; Wh rows are W[E..E+H) of each gate.
__global__ void pack_init_k(const float* __restrict__ Wf, const float* __restrict__ Wi,
                            const float* __restrict__ Wu, const float* __restrict__ Wo)
{
    int idx = blockIdx.x * blockDim.x + threadIdx.x;
    int nt = gridDim.x * blockDim.x;
    if (idx == 0) g_bar = 0u;
    for (int i = idx; i < H_ * B_; i += nt) g_hT[i] = 0.f;
    for (int i = idx; i < NC_ * 256 * 8; i += nt) {
        int c  = i >> 11;
        int hh = (i >> 3) & 255;
        int q  = i & 7;
        int g  = q >> 1, jj = q & 1;
        int col = c * 2 + jj;
        const float* W = (g == 0) ? Wf : (g == 1) ? Wi : (g == 2) ? Wu : Wo;
        g_WhP[i] = W[(E_ + hh) * H_ + col];
    }
}

__device__ __forceinline__ float sigf(float x) { return 1.f / (1.f + expf(-x)); }

// ---------------- persistent LSTM recurrence ----------------
// 128 CTAs x 256 threads. CTA c owns j in {2c, 2c+1}. Threads (b=tid&63, ks=tid>>6)
// compute 8 gate-column partial dots over hh in [ks*64, ks*64+64); reduce in smem;
// threads tid<128 do the cell update and own c[b,j] in a register for all 512 steps.
__global__ void __launch_bounds__(256, 1) recur_k(const float* __restrict__ PRE,
                                                  float* __restrict__ out)
{
    const int c   = blockIdx.x;
    const int tid = threadIdx.x;
    __shared__ __align__(16) float whs[256 * 8];
    __shared__ float part[4 * 64 * 9];          // stride-9 pad: conflict-free

    for (int i = tid; i < 2048; i += 256) whs[i] = g_WhP[c * 2048 + i];

    const int b  = tid & 63;
    const int ks = tid >> 6;                    // 0..3
    const bool epi = (tid < 128);
    const int ejj = (tid >> 6) & 1;
    const int j   = c * 2 + ejj;

    float creg = 0.f, hlast = 0.f;
    __syncthreads();

    for (int t = 0; t < T_; ++t) {
        float a0=0.f,a1=0.f,a2=0.f,a3=0.f,a4=0.f,a5=0.f,a6=0.f,a7=0.f;
        const float*  hp  = g_hT + ks * 64 * 64 + b;
        const float4* wp4 = (const float4*)(whs + ks * 64 * 8);
        #pragma unroll 8
        for (int u = 0; u < 64; ++u) {
            float hv = __ldcg(hp + u * 64);          // L2-coherent (skip stale L1)
            float4 w0 = wp4[u * 2 + 0];
            float4 w1 = wp4[u * 2 + 1];
            a0 += hv * w0.x; a1 += hv * w0.y; a2 += hv * w0.z; a3 += hv * w0.w;
            a4 += hv * w1.x; a5 += hv * w1.y; a6 += hv * w1.z; a7 += hv * w1.w;
        }
        float* pp = part + (ks * 64 + b) * 9;
        pp[0]=a0; pp[1]=a1; pp[2]=a2; pp[3]=a3; pp[4]=a4; pp[5]=a5; pp[6]=a6; pp[7]=a7;
        __syncthreads();

        if (epi) {
            float gate[4];
            #pragma unroll
            for (int g = 0; g < 4; ++g) {
                int q = g * 2 + ejj;
                float s = part[(0 * 64 + b) * 9 + q] + part[(1 * 64 + b) * 9 + q]
                        + part[(2 * 64 + b) * 9 + q] + part[(3 * 64 + b) * 9 + q];
                gate[g] = s + PRE[((long)t * B_ + b) * 1024 + g * 256 + j];
            }
            float fg = sigf(gate[0]);
            float ig = sigf(gate[1]);
            float gg = tanhf(gate[2]);
            float og = sigf(gate[3]);
            creg  = fg * creg + ig * gg;
            hlast = og * tanhf(creg);
            out[((long)t * B_ + b) * H_ + j] = hlast;
            g_hT[j * 64 + b] = hlast;
            __threadfence();                         // publish h before arriving
        }
        __syncthreads();
        if (tid == 0) {
            atomicAdd(&g_bar, 1u);
            unsigned target = (unsigned)(t + 1) * (unsigned)NC_;
            while (*((volatile unsigned*)&g_bar) < target) { }
            __threadfence();
        }
        __syncthreads();
    }

    if (epi) {
        out[(long)TB_ * H_ + b * H_ + j] = hlast;                 // hx
        out[(long)TB_ * H_ + (long)B_ * H_ + b * H_ + j] = creg;  // cx
    }
}

// ---------------- launch ----------------
extern "C" void kernel_launch(void* const* d_in, const int* in_sizes, int n_in,
                              void* d_out, int out_size)
{
    const float* inputs = (const float*)d_in[0];
    const float* rot    = (const float*)d_in[1];
    const float* ent    = (const float*)d_in[2];
    const float* Wf = (const float*)d_in[3];  const float* bf = (const float*)d_in[4];
    const float* Wi = (const float*)d_in[5];  const float* bi = (const float*)d_in[6];
    const float* Wu = (const float*)d_in[7];  const float* bu = (const float*)d_in[8];
    const float* Wo = (const float*)d_in[9];  const float* bo = (const float*)d_in[10];
    const float* Wc = (const float*)d_in[11]; const float* bc = (const float*)d_in[12];
    float* out = (float*)d_out;

    float *Q, *K, *S, *CTX, *CP, *PRE;
    cudaGetSymbolAddress((void**)&Q,   g_Q);
    cudaGetSymbolAddress((void**)&K,   g_K);
    cudaGetSymbolAddress((void**)&S,   g_S);
    cudaGetSymbolAddress((void**)&CTX, g_CTX);
    cudaGetSymbolAddress((void**)&CP,  g_CP);
    cudaGetSymbolAddress((void**)&PRE, g_PRE);

    // pack recurrent weights / zero state early
    pack_init_k<<<256, 256>>>(Wf, Wi, Wu, Wo);

    // Q = X @ rot ; K = X @ ent        (X = inputs as [TB, E])
    gemm_k<false, false, false><<<dim3(E_ / BN, TB_ / BM, 1), 256>>>(
        inputs, rot, Q, nullptr, TB_, E_, E_, E_, E_, E_, 0, 0, 0);
    gemm_k<false, false, false><<<dim3(E_ / BN, TB_ / BM, 1), 256>>>(
        inputs, ent, K, nullptr, TB_, E_, E_, E_, E_, E_, 0, 0, 0);

    // scores_b = Q_b @ K_b^T   (per-batch: row stride B*E, z-offset b*E)
    gemm_k<true, false, false><<<dim3(T_ / BN, T_ / BM, B_), 256>>>(
        Q, K, S, nullptr, T_, T_, E_, B_ * E_, B_ * E_, T_,
        (long)E_, (long)E_, (long)T_ * T_);

    // softmax rows (scale 1/16 fused)
    softmax_k<<<B_ * T_, 128>>>(S);

    // context_b = S_b @ X_b   (X_b rows stride B*E; output back into [T,B,E] layout)
    gemm_k<false, false, false><<<dim3(E_ / BN, T_ / BM, B_), 256>>>(
        S, inputs, CTX, nullptr, T_, E_, T_, T_, B_ * E_, B_ * E_,
        (long)T_ * T_, (long)E_, (long)E_);

    // CP = CTX @ Wc + bc
    gemm_k<false, false, true><<<dim3(H_ / BN, TB_ / BM, 1), 256>>>(
        CTX, Wc, CP, bc, TB_, H_, E_, E_, H_, H_, 0, 0, 0);

    // PRE[:, g*256:(g+1)*256] = X @ Wg[:E] + CP @ Wg[E:] + bg
    const float* Wg[4] = {Wf, Wi, Wu, Wo};
    const float* bg[4] = {bf, bi, bu, bo};
    for (int g = 0; g < 4; ++g) {
        gemm_k<false, false, true><<<dim3(H_ / BN, TB_ / BM, 1), 256>>>(
            inputs, Wg[g], PRE + g * H_, bg[g], TB_, H_, E_, E_, H_, 4 * H_, 0, 0, 0);
        gemm_k<false, true, false><<<dim3(H_ / BN, TB_ / BM, 1), 256>>>(
            CP, Wg[g] + E_ * H_, PRE + g * H_, nullptr, TB_, H_, H_, H_, H_, 4 * H_, 0, 0, 0);
    }

    // persistent recurrence -> outputs, hx, cx
    recur_k<<<NC_, 256>>>(PRE, out);
    (void)in_sizes; (void)n_in; (void)out_size;
}

// round 2
// speedup vs baseline: 1.0323x; 1.0323x over previous
#include <cuda_runtime.h>
#include <math.h>

#define T_  512
#define B_  64
#define E_  256
#define H_  256
#define TB_ (T_ * B_)          // 32768
#define NC_ 128                // recurrence CTAs (each owns 2 h-columns)

// ---------------- static device scratch (no allocations allowed) ----------------
__device__ float g_Q  [TB_ * E_];
__device__ float g_K  [TB_ * E_];
__device__ float g_S  [B_ * T_ * T_];
__device__ float g_CTX[TB_ * E_];
__device__ float g_CP [TB_ * H_];
__device__ float g_PRE[(long)TB_ * 4 * H_];
__device__ float g_Wall[512 * 1024];       // packed [Wf|Wi|Wu|Wo] as (512, 1024)
__device__ float g_ball[1024];
__device__ float g_WhP[NC_ * 256 * 8];     // packed recurrent weights per CTA
__device__ float g_hT [H_ * B_];           // h transposed [j][b]
__device__ unsigned g_bar;

// ---------------- tf32 split helper ----------------
__device__ __forceinline__ void split_tf32(float x, unsigned& hi, unsigned& lo)
{
    unsigned h;
    asm("cvt.rna.tf32.f32 %0, %1;" : "=r"(h) : "f"(x));
    float lf = x - __uint_as_float(h);
    unsigned l;
    asm("cvt.rna.tf32.f32 %0, %1;" : "=r"(l) : "f"(lf));
    hi = h; lo = l;
}

#define MMA_TF32(c, a, b)                                                         \
    asm volatile("mma.sync.aligned.m16n8k8.row.col.f32.tf32.tf32.f32 "            \
                 "{%0,%1,%2,%3},{%4,%5,%6,%7},{%8,%9},{%0,%1,%2,%3};"             \
                 : "+f"(c[0]), "+f"(c[1]), "+f"(c[2]), "+f"(c[3])                 \
                 : "r"(a[0]), "r"(a[1]), "r"(a[2]), "r"(a[3]),                    \
                   "r"(b[0]), "r"(b[1]))

// ---------------- tensor-core tf32 GEMM (3x split, fp32-level accuracy) -------
// C[M,N] = A[M,K] @ B (+bias). NT: B is row-major [N,K] (C = A·B^T).
// CONCAT: A cols 0..255 from A, cols 256..511 from A2 (both lda=256).
// Block tile 128x64x16, 256 threads, 8 warps in 4(m) x 2(n), warp tile 32x32.
template<bool NT, bool BIAS, bool CONCAT>
__global__ void __launch_bounds__(256, 2) gemm_tc(
    const float* __restrict__ A, const float* __restrict__ A2,
    const float* __restrict__ B, float* __restrict__ C,
    const float* __restrict__ bias,
    int M, int N, int K, int lda, int ldb, int ldc,
    long sA, long sB, long sC)
{
    A += (long)blockIdx.z * sA;
    B += (long)blockIdx.z * sB;
    C += (long)blockIdx.z * sC;

    __shared__ unsigned As_hi[128][20], As_lo[128][20];
    __shared__ unsigned Bs_hi[16][72],  Bs_lo[16][72];

    const int tid  = threadIdx.x;
    const int lane = tid & 31;
    const int warp = tid >> 5;
    const int m0 = blockIdx.y * 128;
    const int n0 = blockIdx.x * 64;
    const int wm = (warp >> 1) * 32;
    const int wn = (warp & 1) * 32;
    const int gq = lane >> 2;     // groupID 0..7
    const int tg = lane & 3;      // thread-in-group 0..3

    const int ar  = tid >> 2;         // A row 0..63 (and +64)
    const int ac  = (tid & 3) * 4;    // A col quad
    const int bkr = tid >> 4;         // NN B row 0..15
    const int bnc = (tid & 15) * 4;
    const int bnr = tid >> 2;         // NT B row 0..63
    const int bkc = (tid & 3) * 4;

    float acc[2][4][4];
    #pragma unroll
    for (int i = 0; i < 2; ++i)
        #pragma unroll
        for (int j = 0; j < 4; ++j)
            #pragma unroll
            for (int q = 0; q < 4; ++q) acc[i][j][q] = 0.f;

    for (int k0 = 0; k0 < K; k0 += 16) {
        const float* Ab = A;
        int kc = k0;
        if (CONCAT) { if (k0 >= 256) { Ab = A2; kc = k0 - 256; } }

        float4 va0 = *(const float4*)(Ab + (long)(m0 + ar) * lda + kc + ac);
        float4 va1 = *(const float4*)(Ab + (long)(m0 + ar + 64) * lda + kc + ac);
        float4 vb;
        if (NT) vb = *(const float4*)(B + (long)(n0 + bnr) * ldb + k0 + bkc);
        else    vb = *(const float4*)(B + (long)(k0 + bkr) * ldb + n0 + bnc);

        __syncthreads();
        {
            float av[4] = {va0.x, va0.y, va0.z, va0.w};
            #pragma unroll
            for (int q = 0; q < 4; ++q)
                split_tf32(av[q], As_hi[ar][ac + q], As_lo[ar][ac + q]);
            float aw[4] = {va1.x, va1.y, va1.z, va1.w};
            #pragma unroll
            for (int q = 0; q < 4; ++q)
                split_tf32(aw[q], As_hi[ar + 64][ac + q], As_lo[ar + 64][ac + q]);
            float bv[4] = {vb.x, vb.y, vb.z, vb.w};
            if (NT) {
                #pragma unroll
                for (int q = 0; q < 4; ++q)
                    split_tf32(bv[q], Bs_hi[bkc + q][bnr], Bs_lo[bkc + q][bnr]);
            } else {
                #pragma unroll
                for (int q = 0; q < 4; ++q)
                    split_tf32(bv[q], Bs_hi[bkr][bnc + q], Bs_lo[bkr][bnc + q]);
            }
        }
        __syncthreads();

        #pragma unroll
        for (int kk = 0; kk < 16; kk += 8) {
            unsigned ah[2][4], al[2][4], bh[4][2], bl[4][2];
            #pragma unroll
            for (int i = 0; i < 2; ++i) {
                int r = wm + i * 16 + gq;
                ah[i][0] = As_hi[r    ][kk + tg];
                ah[i][1] = As_hi[r + 8][kk + tg];
                ah[i][2] = As_hi[r    ][kk + tg + 4];
                ah[i][3] = As_hi[r + 8][kk + tg + 4];
                al[i][0] = As_lo[r    ][kk + tg];
                al[i][1] = As_lo[r + 8][kk + tg];
                al[i][2] = As_lo[r    ][kk + tg + 4];
                al[i][3] = As_lo[r + 8][kk + tg + 4];
            }
            #pragma unroll
            for (int j = 0; j < 4; ++j) {
                int n = wn + j * 8 + gq;
                bh[j][0] = Bs_hi[kk + tg    ][n];
                bh[j][1] = Bs_hi[kk + tg + 4][n];
                bl[j][0] = Bs_lo[kk + tg    ][n];
                bl[j][1] = Bs_lo[kk + tg + 4][n];
            }
            #pragma unroll
            for (int i = 0; i < 2; ++i)
                #pragma unroll
                for (int j = 0; j < 4; ++j) {
                    MMA_TF32(acc[i][j], ah[i], bh[j]);
                    MMA_TF32(acc[i][j], al[i], bh[j]);
                    MMA_TF32(acc[i][j], ah[i], bl[j]);
                }
        }
    }

    #pragma unroll
    for (int i = 0; i < 2; ++i)
        #pragma unroll
        for (int j = 0; j < 4; ++j) {
            int m = m0 + wm + i * 16 + gq;
            int n = n0 + wn + j * 8 + 2 * tg;
            float2 v0 = make_float2(acc[i][j][0], acc[i][j][1]);
            float2 v1 = make_float2(acc[i][j][2], acc[i][j][3]);
            if (BIAS) {
                float b0 = bias[n], b1 = bias[n + 1];
                v0.x += b0; v0.y += b1;
                v1.x += b0; v1.y += b1;
            }
            *(float2*)(C + (long)m * ldc + n)       = v0;
            *(float2*)(C + (long)(m + 8) * ldc + n) = v1;
        }
}

// ---------------- softmax over rows of length 512 (scale 1/sqrt(256)) ----------
__global__ void __launch_bounds__(128) softmax_k(float* __restrict__ S)
{
    float* p = S + (long)blockIdx.x * 512;
    int tid = threadIdx.x;
    float v[4];
    float m = -1e30f;
    #pragma unroll
    for (int i = 0; i < 4; ++i) { v[i] = p[tid + 128 * i] * 0.0625f; m = fmaxf(m, v[i]); }
    __shared__ float red[128];
    red[tid] = m; __syncthreads();
    for (int s = 64; s > 0; s >>= 1) { if (tid < s) red[tid] = fmaxf(red[tid], red[tid + s]); __syncthreads(); }
    m = red[0]; __syncthreads();
    float sum = 0.f;
    #pragma unroll
    for (int i = 0; i < 4; ++i) { v[i] = expf(v[i] - m); sum += v[i]; }
    red[tid] = sum; __syncthreads();
    for (int s = 64; s > 0; s >>= 1) { if (tid < s) red[tid] += red[tid + s]; __syncthreads(); }
    float inv = 1.f / red[0];
    #pragma unroll
    for (int i = 0; i < 4; ++i) p[tid + 128 * i] = v[i] * inv;
}

// ---------------- pack weights + init state ----------------
__global__ void pack_init_k(const float* __restrict__ Wf, const float* __restrict__ Wi,
                            const float* __restrict__ Wu, const float* __restrict__ Wo,
                            const float* __restrict__ bf, const float* __restrict__ bi,
                            const float* __restrict__ bu, const float* __restrict__ bo)
{
    int idx = blockIdx.x * blockDim.x + threadIdx.x;
    int nt = gridDim.x * blockDim.x;
    if (idx == 0) g_bar = 0u;
    for (int i = idx; i < H_ * B_; i += nt) g_hT[i] = 0.f;
    // recurrence weights: g_WhP[c][hh][q], q=g*2+jj, col j=c*2+jj, rows E..E+H
    for (int i = idx; i < NC_ * 256 * 8; i += nt) {
        int c  = i >> 11;
        int hh = (i >> 3) & 255;
        int q  = i & 7;
        int g  = q >> 1, jj = q & 1;
        int col = c * 2 + jj;
        const float* W = (g == 0) ? Wf : (g == 1) ? Wi : (g == 2) ? Wu : Wo;
        g_WhP[i] = W[(E_ + hh) * H_ + col];
    }
    // fused PRE weights: g_Wall[k][g*256+j] = Wg[k][j], k in [0,512)
    for (int i = idx; i < 512 * 1024; i += nt) {
        int k = i >> 10;
        int col = i & 1023;
        int g = col >> 8, j = col & 255;
        const float* W = (g == 0) ? Wf : (g == 1) ? Wi : (g == 2) ? Wu : Wo;
        g_Wall[i] = W[k * 256 + j];
    }
    for (int i = idx; i < 1024; i += nt) {
        int g = i >> 8;
        const float* b = (g == 0) ? bf : (g == 1) ? bi : (g == 2) ? bu : bo;
        g_ball[i] = b[i & 255];
    }
}

__device__ __forceinline__ float sigf(float x) { return 1.f / (1.f + expf(-x)); }

// ---------------- persistent LSTM recurrence ----------------
__global__ void __launch_bounds__(256, 1) recur_k(const float* __restrict__ PRE,
                                                  float* __restrict__ out)
{
    const int c   = blockIdx.x;
    const int tid = threadIdx.x;
    __shared__ __align__(16) float whs[256 * 8];
    __shared__ float part[4 * 64 * 9];

    for (int i = tid; i < 2048; i += 256) whs[i] = g_WhP[c * 2048 + i];

    const int b  = tid & 63;
    const int ks = tid >> 6;
    const bool epi = (tid < 128);
    const int ejj = (tid >> 6) & 1;
    const int j   = c * 2 + ejj;

    float creg = 0.f, hlast = 0.f;
    __syncthreads();

    for (int t = 0; t < T_; ++t) {
        float a0=0.f,a1=0.f,a2=0.f,a3=0.f,a4=0.f,a5=0.f,a6=0.f,a7=0.f;
        const float*  hp  = g_hT + ks * 64 * 64 + b;
        const float4* wp4 = (const float4*)(whs + ks * 64 * 8);
        #pragma unroll 8
        for (int u = 0; u < 64; ++u) {
            float hv = __ldcg(hp + u * 64);
            float4 w0 = wp4[u * 2 + 0];
            float4 w1 = wp4[u * 2 + 1];
            a0 += hv * w0.x; a1 += hv * w0.y; a2 += hv * w0.z; a3 += hv * w0.w;
            a4 += hv * w1.x; a5 += hv * w1.y; a6 += hv * w1.z; a7 += hv * w1.w;
        }
        float* pp = part + (ks * 64 + b) * 9;
        pp[0]=a0; pp[1]=a1; pp[2]=a2; pp[3]=a3; pp[4]=a4; pp[5]=a5; pp[6]=a6; pp[7]=a7;
        __syncthreads();

        if (epi) {
            float gate[4];
            #pragma unroll
            for (int g = 0; g < 4; ++g) {
                int q = g * 2 + ejj;
                float s = part[(0 * 64 + b) * 9 + q] + part[(1 * 64 + b) * 9 + q]
                        + part[(2 * 64 + b) * 9 + q] + part[(3 * 64 + b) * 9 + q];
                gate[g] = s + PRE[((long)t * B_ + b) * 1024 + g * 256 + j];
            }
            float fg = sigf(gate[0]);
            float ig = sigf(gate[1]);
            float gg = tanhf(gate[2]);
            float og = sigf(gate[3]);
            creg  = fg * creg + ig * gg;
            hlast = og * tanhf(creg);
            out[((long)t * B_ + b) * H_ + j] = hlast;
            g_hT[j * 64 + b] = hlast;
            __threadfence();
        }
        __syncthreads();
        if (tid == 0) {
            atomicAdd(&g_bar, 1u);
            unsigned target = (unsigned)(t + 1) * (unsigned)NC_;
            while (*((volatile unsigned*)&g_bar) < target) { }
            __threadfence();
        }
        __syncthreads();
    }

    if (epi) {
        out[(long)TB_ * H_ + b * H_ + j] = hlast;
        out[(long)TB_ * H_ + (long)B_ * H_ + b * H_ + j] = creg;
    }
}

// ---------------- launch ----------------
extern "C" void kernel_launch(void* const* d_in, const int* in_sizes, int n_in,
                              void* d_out, int out_size)
{
    const float* inputs = (const float*)d_in[0];
    const float* rot    = (const float*)d_in[1];
    const float* ent    = (const float*)d_in[2];
    const float* Wf = (const float*)d_in[3];  const float* bf = (const float*)d_in[4];
    const float* Wi = (const float*)d_in[5];  const float* bi = (const float*)d_in[6];
    const float* Wu = (const float*)d_in[7];  const float* bu = (const float*)d_in[8];
    const float* Wo = (const float*)d_in[9];  const float* bo = (const float*)d_in[10];
    const float* Wc = (const float*)d_in[11]; const float* bc = (const float*)d_in[12];
    float* out = (float*)d_out;

    float *Q, *K, *S, *CTX, *CP, *PRE, *Wall, *ball;
    cudaGetSymbolAddress((void**)&Q,    g_Q);
    cudaGetSymbolAddress((void**)&K,    g_K);
    cudaGetSymbolAddress((void**)&S,    g_S);
    cudaGetSymbolAddress((void**)&CTX,  g_CTX);
    cudaGetSymbolAddress((void**)&CP,   g_CP);
    cudaGetSymbolAddress((void**)&PRE,  g_PRE);
    cudaGetSymbolAddress((void**)&Wall, g_Wall);
    cudaGetSymbolAddress((void**)&ball, g_ball);

    pack_init_k<<<256, 256>>>(Wf, Wi, Wu, Wo, bf, bi, bu, bo);

    // Q = X @ rot ; K = X @ ent
    gemm_tc<false, false, false><<<dim3(E_ / 64, TB_ / 128, 1), 256>>>(
        inputs, nullptr, rot, Q, nullptr, TB_, E_, E_, E_, E_, E_, 0, 0, 0);
    gemm_tc<false, false, false><<<dim3(E_ / 64, TB_ / 128, 1), 256>>>(
        inputs, nullptr, ent, K, nullptr, TB_, E_, E_, E_, E_, E_, 0, 0, 0);

    // scores_b = Q_b @ K_b^T
    gemm_tc<true, false, false><<<dim3(T_ / 64, T_ / 128, B_), 256>>>(
        Q, nullptr, K, S, nullptr, T_, T_, E_, B_ * E_, B_ * E_, T_,
        (long)E_, (long)E_, (long)T_ * T_);

    softmax_k<<<B_ * T_, 128>>>(S);

    // context_b = S_b @ X_b
    gemm_tc<false, false, false><<<dim3(E_ / 64, T_ / 128, B_), 256>>>(
        S, nullptr, inputs, CTX, nullptr, T_, E_, T_, T_, B_ * E_, B_ * E_,
        (long)T_ * T_, (long)E_, (long)E_);

    // CP = CTX @ Wc + bc
    gemm_tc<false, true, false><<<dim3(H_ / 64, TB_ / 128, 1), 256>>>(
        CTX, nullptr, Wc, CP, bc, TB_, H_, E_, E_, H_, H_, 0, 0, 0);

    // PRE = [X | CP] @ Wall + ball   (single fused K=512 GEMM)
    gemm_tc<false, true, true><<<dim3(1024 / 64, TB_ / 128, 1), 256>>>(
        inputs, CP, Wall, PRE, ball, TB_, 1024, 512, E_, 1024, 1024, 0, 0, 0);

    // persistent recurrence -> outputs, hx, cx
    recur_k<<<NC_, 256>>>(PRE, out);
    (void)in_sizes; (void)n_in; (void)out_size;
}

// round 3
// speedup vs baseline: 1.1931x; 1.1558x over previous
#include <cuda_runtime.h>
#include <math.h>

#define T_  512
#define B_  64
#define E_  256
#define H_  256
#define TB_ (T_ * B_)          // 32768
#define CLU 8                  // CTAs per cluster
#define BG  4                  // batch elements per cluster

// ---------------- static device scratch (no allocations allowed) ----------------
__device__ float g_Q  [TB_ * E_];
__device__ float g_K  [TB_ * E_];
__device__ float g_S  [B_ * T_ * T_];
__device__ float g_CTX[TB_ * E_];
__device__ float g_CP [TB_ * H_];
__device__ float g_PRE[(long)TB_ * 4 * H_];
__device__ float g_Wall[512 * 1024];       // packed [Wf|Wi|Wu|Wo] as (512, 1024)
__device__ float g_ball[1024];
__device__ float g_WhC[CLU * 256 * 32 * 4];// recurrent W: [rank][k][jl][gate4]

// ---------------- tf32 split helper ----------------
__device__ __forceinline__ void split_tf32(float x, unsigned& hi, unsigned& lo)
{
    unsigned h;
    asm("cvt.rna.tf32.f32 %0, %1;" : "=r"(h) : "f"(x));
    float lf = x - __uint_as_float(h);
    unsigned l;
    asm("cvt.rna.tf32.f32 %0, %1;" : "=r"(l) : "f"(lf));
    hi = h; lo = l;
}

#define MMA_TF32(c, a, b)                                                         \
    asm volatile("mma.sync.aligned.m16n8k8.row.col.f32.tf32.tf32.f32 "            \
                 "{%0,%1,%2,%3},{%4,%5,%6,%7},{%8,%9},{%0,%1,%2,%3};"             \
                 : "+f"(c[0]), "+f"(c[1]), "+f"(c[2]), "+f"(c[3])                 \
                 : "r"(a[0]), "r"(a[1]), "r"(a[2]), "r"(a[3]),                    \
                   "r"(b[0]), "r"(b[1]))

// ---------------- tensor-core tf32 GEMM (3x split, fp32-level accuracy) -------
// C[M,N] = A[M,K] @ B (+bias). NT: B is row-major [N,K] (C = A·B^T).
// CONCAT: A cols 0..255 from A, cols 256..511 from A2 (both lda=256).
template<bool NT, bool BIAS, bool CONCAT>
__global__ void __launch_bounds__(256, 2) gemm_tc(
    const float* __restrict__ A, const float* __restrict__ A2,
    const float* __restrict__ B, float* __restrict__ C,
    const float* __restrict__ bias,
    int M, int N, int K, int lda, int ldb, int ldc,
    long sA, long sB, long sC)
{
    A += (long)blockIdx.z * sA;
    B += (long)blockIdx.z * sB;
    C += (long)blockIdx.z * sC;

    __shared__ unsigned As_hi[128][20], As_lo[128][20];
    __shared__ unsigned Bs_hi[16][72],  Bs_lo[16][72];

    const int tid  = threadIdx.x;
    const int lane = tid & 31;
    const int warp = tid >> 5;
    const int m0 = blockIdx.y * 128;
    const int n0 = blockIdx.x * 64;
    const int wm = (warp >> 1) * 32;
    const int wn = (warp & 1) * 32;
    const int gq = lane >> 2;
    const int tg = lane & 3;

    const int ar  = tid >> 2;
    const int ac  = (tid & 3) * 4;
    const int bkr = tid >> 4;
    const int bnc = (tid & 15) * 4;
    const int bnr = tid >> 2;
    const int bkc = (tid & 3) * 4;

    float acc[2][4][4];
    #pragma unroll
    for (int i = 0; i < 2; ++i)
        #pragma unroll
        for (int j = 0; j < 4; ++j)
            #pragma unroll
            for (int q = 0; q < 4; ++q) acc[i][j][q] = 0.f;

    for (int k0 = 0; k0 < K; k0 += 16) {
        const float* Ab = A;
        int kc = k0;
        if (CONCAT) { if (k0 >= 256) { Ab = A2; kc = k0 - 256; } }

        float4 va0 = *(const float4*)(Ab + (long)(m0 + ar) * lda + kc + ac);
        float4 va1 = *(const float4*)(Ab + (long)(m0 + ar + 64) * lda + kc + ac);
        float4 vb;
        if (NT) vb = *(const float4*)(B + (long)(n0 + bnr) * ldb + k0 + bkc);
        else    vb = *(const float4*)(B + (long)(k0 + bkr) * ldb + n0 + bnc);

        __syncthreads();
        {
            float av[4] = {va0.x, va0.y, va0.z, va0.w};
            #pragma unroll
            for (int q = 0; q < 4; ++q)
                split_tf32(av[q], As_hi[ar][ac + q], As_lo[ar][ac + q]);
            float aw[4] = {va1.x, va1.y, va1.z, va1.w};
            #pragma unroll
            for (int q = 0; q < 4; ++q)
                split_tf32(aw[q], As_hi[ar + 64][ac + q], As_lo[ar + 64][ac + q]);
            float bv[4] = {vb.x, vb.y, vb.z, vb.w};
            if (NT) {
                #pragma unroll
                for (int q = 0; q < 4; ++q)
                    split_tf32(bv[q], Bs_hi[bkc + q][bnr], Bs_lo[bkc + q][bnr]);
            } else {
                #pragma unroll
                for (int q = 0; q < 4; ++q)
                    split_tf32(bv[q], Bs_hi[bkr][bnc + q], Bs_lo[bkr][bnc + q]);
            }
        }
        __syncthreads();

        #pragma unroll
        for (int kk = 0; kk < 16; kk += 8) {
            unsigned ah[2][4], al[2][4], bh[4][2], bl[4][2];
            #pragma unroll
            for (int i = 0; i < 2; ++i) {
                int r = wm + i * 16 + gq;
                ah[i][0] = As_hi[r    ][kk + tg];
                ah[i][1] = As_hi[r + 8][kk + tg];
                ah[i][2] = As_hi[r    ][kk + tg + 4];
                ah[i][3] = As_hi[r + 8][kk + tg + 4];
                al[i][0] = As_lo[r    ][kk + tg];
                al[i][1] = As_lo[r + 8][kk + tg];
                al[i][2] = As_lo[r    ][kk + tg + 4];
                al[i][3] = As_lo[r + 8][kk + tg + 4];
            }
            #pragma unroll
            for (int j = 0; j < 4; ++j) {
                int n = wn + j * 8 + gq;
                bh[j][0] = Bs_hi[kk + tg    ][n];
                bh[j][1] = Bs_hi[kk + tg + 4][n];
                bl[j][0] = Bs_lo[kk + tg    ][n];
                bl[j][1] = Bs_lo[kk + tg + 4][n];
            }
            #pragma unroll
            for (int i = 0; i < 2; ++i)
                #pragma unroll
                for (int j = 0; j < 4; ++j) {
                    MMA_TF32(acc[i][j], ah[i], bh[j]);
                    MMA_TF32(acc[i][j], al[i], bh[j]);
                    MMA_TF32(acc[i][j], ah[i], bl[j]);
                }
        }
    }

    #pragma unroll
    for (int i = 0; i < 2; ++i)
        #pragma unroll
        for (int j = 0; j < 4; ++j) {
            int m = m0 + wm + i * 16 + gq;
            int n = n0 + wn + j * 8 + 2 * tg;
            float2 v0 = make_float2(acc[i][j][0], acc[i][j][1]);
            float2 v1 = make_float2(acc[i][j][2], acc[i][j][3]);
            if (BIAS) {
                float b0 = bias[n], b1 = bias[n + 1];
                v0.x += b0; v0.y += b1;
                v1.x += b0; v1.y += b1;
            }
            *(float2*)(C + (long)m * ldc + n)       = v0;
            *(float2*)(C + (long)(m + 8) * ldc + n) = v1;
        }
}

// ---------------- softmax over rows of length 512 (scale 1/sqrt(256)) ----------
__global__ void __launch_bounds__(128) softmax_k(float* __restrict__ S)
{
    float* p = S + (long)blockIdx.x * 512;
    int tid = threadIdx.x;
    float v[4];
    float m = -1e30f;
    #pragma unroll
    for (int i = 0; i < 4; ++i) { v[i] = p[tid + 128 * i] * 0.0625f; m = fmaxf(m, v[i]); }
    __shared__ float red[128];
    red[tid] = m; __syncthreads();
    for (int s = 64; s > 0; s >>= 1) { if (tid < s) red[tid] = fmaxf(red[tid], red[tid + s]); __syncthreads(); }
    m = red[0]; __syncthreads();
    float sum = 0.f;
    #pragma unroll
    for (int i = 0; i < 4; ++i) { v[i] = expf(v[i] - m); sum += v[i]; }
    red[tid] = sum; __syncthreads();
    for (int s = 64; s > 0; s >>= 1) { if (tid < s) red[tid] += red[tid + s]; __syncthreads(); }
    float inv = 1.f / red[0];
    #pragma unroll
    for (int i = 0; i < 4; ++i) p[tid + 128 * i] = v[i] * inv;
}

// ---------------- pack weights ----------------
__global__ void pack_init_k(const float* __restrict__ Wf, const float* __restrict__ Wi,
                            const float* __restrict__ Wu, const float* __restrict__ Wo,
                            const float* __restrict__ bf, const float* __restrict__ bi,
                            const float* __restrict__ bu, const float* __restrict__ bo)
{
    int idx = blockIdx.x * blockDim.x + threadIdx.x;
    int nt = gridDim.x * blockDim.x;
    // recurrent weights for cluster kernel: [rank][k][jl][g]
    for (int i = idx; i < CLU * 256 * 32 * 4; i += nt) {
        int r  = i >> 15;
        int k  = (i >> 7) & 255;
        int jl = (i >> 2) & 31;
        int g  = i & 3;
        const float* W = (g == 0) ? Wf : (g == 1) ? Wi : (g == 2) ? Wu : Wo;
        g_WhC[i] = W[(E_ + k) * H_ + r * 32 + jl];
    }
    // fused PRE weights: g_Wall[k][g*256+j]
    for (int i = idx; i < 512 * 1024; i += nt) {
        int k = i >> 10;
        int col = i & 1023;
        int g = col >> 8, j = col & 255;
        const float* W = (g == 0) ? Wf : (g == 1) ? Wi : (g == 2) ? Wu : Wo;
        g_Wall[i] = W[k * 256 + j];
    }
    for (int i = idx; i < 1024; i += nt) {
        int g = i >> 8;
        const float* b = (g == 0) ? bf : (g == 1) ? bi : (g == 2) ? bu : bo;
        g_ball[i] = b[i & 255];
    }
}

__device__ __forceinline__ float sigf(float x)  { return 1.f / (1.f + __expf(-x)); }
__device__ __forceinline__ float tanhf_(float x){ return 2.f / (1.f + __expf(-2.f * x)) - 1.f; }

// ---------------- cluster LSTM recurrence ----------------
// 16 clusters x 8 CTAs. Cluster = one batch group of 4. CTA rank r owns gate
// columns j in [32r, 32r+32) (all 4 gates), Wh slice resident in smem (128KB).
// h double-buffered in smem, exchanged via DSMEM + barrier.cluster each step.
__global__ void __launch_bounds__(256, 1) __cluster_dims__(CLU, 1, 1)
recur2_k(const float* __restrict__ PRE, float* __restrict__ out)
{
    extern __shared__ float4 sm4[];
    float4* ws4   = sm4;            // [256 k][32 jl] (gate4)   = 8192 float4
    float4* hs4   = sm4 + 8192;     // [2 buf][256 k] (b4)      = 512 float4
    float4* part4 = sm4 + 8704;     // [4 b][8 ks][32 jl]       = 1024 float4

    const int tid = threadIdx.x;
    unsigned rank;
    asm("mov.u32 %0, %%cluster_ctarank;" : "=r"(rank));
    const int bg0 = (blockIdx.x / CLU) * BG;

    // load this rank's W slice into smem; zero h buffers
    const float4* Wsrc = (const float4*)g_WhC + (long)rank * 8192;
    for (int m = tid; m < 8192; m += 256) ws4[m] = Wsrc[m];
    for (int m = tid; m < 512; m += 256) hs4[m] = make_float4(0.f, 0.f, 0.f, 0.f);

    const int jl = tid & 31;        // compute: gate-column within slice
    const int ks = tid >> 5;        // compute: k-segment 0..7 (32 k each)

    const bool epi = tid < 128;
    const int  eb  = tid & 3;       // epi: batch-in-group
    const int  ejl = tid >> 2;      // epi: jl 0..31
    const int  jg  = rank * 32 + ejl;

    float creg = 0.f, hlast = 0.f;
    float pre0 = 0.f, pre1 = 0.f, pre2 = 0.f, pre3 = 0.f;
    if (epi) {
        const float* pp = PRE + ((long)0 * B_ + bg0 + eb) * 1024 + jg;
        pre0 = pp[0]; pre1 = pp[256]; pre2 = pp[512]; pre3 = pp[768];
    }

    const unsigned hs_u32 = (unsigned)__cvta_generic_to_shared(hs4);

    // init sync: smem (W, h) ready in all cluster CTAs before DSMEM traffic
    asm volatile("barrier.cluster.arrive.aligned;" ::: "memory");
    asm volatile("barrier.cluster.wait.aligned;"   ::: "memory");

    for (int t = 0; t < T_; ++t) {
        const int buf = t & 1;
        const float4* hp = hs4 + buf * 256 + ks * 32;
        const float4* wp = ws4 + (ks * 32) * 32 + jl;

        float4 a0 = {0,0,0,0}, a1 = {0,0,0,0}, a2 = {0,0,0,0}, a3 = {0,0,0,0};
        #pragma unroll 8
        for (int u = 0; u < 32; ++u) {
            float4 hv = hp[u];          // broadcast across warp (1 wf)
            float4 wv = wp[u * 32];     // consecutive float4 per lane (4 wf)
            a0.x += hv.x*wv.x; a0.y += hv.x*wv.y; a0.z += hv.x*wv.z; a0.w += hv.x*wv.w;
            a1.x += hv.y*wv.x; a1.y += hv.y*wv.y; a1.z += hv.y*wv.z; a1.w += hv.y*wv.w;
            a2.x += hv.z*wv.x; a2.y += hv.z*wv.y; a2.z += hv.z*wv.z; a2.w += hv.z*wv.w;
            a3.x += hv.w*wv.x; a3.y += hv.w*wv.y; a3.z += hv.w*wv.z; a3.w += hv.w*wv.w;
        }
        part4[(0 * 8 + ks) * 32 + jl] = a0;
        part4[(1 * 8 + ks) * 32 + jl] = a1;
        part4[(2 * 8 + ks) * 32 + jl] = a2;
        part4[(3 * 8 + ks) * 32 + jl] = a3;
        __syncthreads();

        if (epi) {
            float4 s = part4[(eb * 8 + 0) * 32 + ejl];
            #pragma unroll
            for (int q = 1; q < 8; ++q) {
                float4 p = part4[(eb * 8 + q) * 32 + ejl];
                s.x += p.x; s.y += p.y; s.z += p.z; s.w += p.w;
            }
            float fg = sigf  (s.x + pre0);
            float ig = sigf  (s.y + pre1);
            float ug = tanhf_(s.z + pre2);
            float og = sigf  (s.w + pre3);
            creg  = fg * creg + ig * ug;
            hlast = og * tanhf_(creg);
            out[((long)t * B_ + bg0 + eb) * H_ + jg] = hlast;

            // publish h to hs[buf^1] of every cluster CTA (incl. self) via DSMEM
            unsigned laddr = hs_u32 + ((((buf ^ 1) * 256 + jg) * 4 + eb) << 2);
            #pragma unroll
            for (int r2 = 0; r2 < CLU; ++r2) {
                unsigned ra;
                asm volatile("mapa.shared::cluster.u32 %0, %1, %2;"
                             : "=r"(ra) : "r"(laddr), "r"(r2));
                asm volatile("st.shared::cluster.f32 [%0], %1;"
                             :: "r"(ra), "f"(hlast) : "memory");
            }

            // prefetch PRE for next step (latency hidden behind barrier+compute)
            int tn = (t < T_ - 1) ? t + 1 : t;
            const float* pp = PRE + ((long)tn * B_ + bg0 + eb) * 1024 + jg;
            pre0 = pp[0]; pre1 = pp[256]; pre2 = pp[512]; pre3 = pp[768];
        }

        asm volatile("barrier.cluster.arrive.aligned;" ::: "memory");
        asm volatile("barrier.cluster.wait.aligned;"   ::: "memory");
    }

    if (epi) {
        out[(long)TB_ * H_ + (bg0 + eb) * H_ + jg] = hlast;                 // hx
        out[(long)TB_ * H_ + (long)B_ * H_ + (bg0 + eb) * H_ + jg] = creg;  // cx
    }
}

// ---------------- launch ----------------
extern "C" void kernel_launch(void* const* d_in, const int* in_sizes, int n_in,
                              void* d_out, int out_size)
{
    const float* inputs = (const float*)d_in[0];
    const float* rot    = (const float*)d_in[1];
    const float* ent    = (const float*)d_in[2];
    const float* Wf = (const float*)d_in[3];  const float* bf = (const float*)d_in[4];
    const float* Wi = (const float*)d_in[5];  const float* bi = (const float*)d_in[6];
    const float* Wu = (const float*)d_in[7];  const float* bu = (const float*)d_in[8];
    const float* Wo = (const float*)d_in[9];  const float* bo = (const float*)d_in[10];
    const float* Wc = (const float*)d_in[11]; const float* bc = (const float*)d_in[12];
    float* out = (float*)d_out;

    float *Q, *K, *S, *CTX, *CP, *PRE, *Wall, *ball;
    cudaGetSymbolAddress((void**)&Q,    g_Q);
    cudaGetSymbolAddress((void**)&K,    g_K);
    cudaGetSymbolAddress((void**)&S,    g_S);
    cudaGetSymbolAddress((void**)&CTX,  g_CTX);
    cudaGetSymbolAddress((void**)&CP,   g_CP);
    cudaGetSymbolAddress((void**)&PRE,  g_PRE);
    cudaGetSymbolAddress((void**)&Wall, g_Wall);
    cudaGetSymbolAddress((void**)&ball, g_ball);

    const int RSMEM = 9728 * 16;  // 152 KB dynamic smem for recur2_k
    cudaFuncSetAttribute(recur2_k, cudaFuncAttributeMaxDynamicSharedMemorySize, RSMEM);

    pack_init_k<<<256, 256>>>(Wf, Wi, Wu, Wo, bf, bi, bu, bo);

    // Q = X @ rot ; K = X @ ent
    gemm_tc<false, false, false><<<dim3(E_ / 64, TB_ / 128, 1), 256>>>(
        inputs, nullptr, rot, Q, nullptr, TB_, E_, E_, E_, E_, E_, 0, 0, 0);
    gemm_tc<false, false, false><<<dim3(E_ / 64, TB_ / 128, 1), 256>>>(
        inputs, nullptr, ent, K, nullptr, TB_, E_, E_, E_, E_, E_, 0, 0, 0);

    // scores_b = Q_b @ K_b^T
    gemm_tc<true, false, false><<<dim3(T_ / 64, T_ / 128, B_), 256>>>(
        Q, nullptr, K, S, nullptr, T_, T_, E_, B_ * E_, B_ * E_, T_,
        (long)E_, (long)E_, (long)T_ * T_);

    softmax_k<<<B_ * T_, 128>>>(S);

    // context_b = S_b @ X_b
    gemm_tc<false, false, false><<<dim3(E_ / 64, T_ / 128, B_), 256>>>(
        S, nullptr, inputs, CTX, nullptr, T_, E_, T_, T_, B_ * E_, B_ * E_,
        (long)T_ * T_, (long)E_, (long)E_);

    // CP = CTX @ Wc + bc
    gemm_tc<false, true, false><<<dim3(H_ / 64, TB_ / 128, 1), 256>>>(
        CTX, nullptr, Wc, CP, bc, TB_, H_, E_, E_, H_, H_, 0, 0, 0);

    // PRE = [X | CP] @ Wall + ball   (single fused K=512 GEMM)
    gemm_tc<false, true, true><<<dim3(1024 / 64, TB_ / 128, 1), 256>>>(
        inputs, CP, Wall, PRE, ball, TB_, 1024, 512, E_, 1024, 1024, 0, 0, 0);

    // cluster-based recurrence -> outputs, hx, cx
    recur2_k<<<128, 256, RSMEM>>>(PRE, out);
    (void)in_sizes; (void)n_in; (void)out_size;
}